// round 12
// baseline (speedup 1.0000x reference)
#include <cuda_runtime.h>
#include <math.h>

#define Bq 16
#define Hq 128
#define Lq 8192
#define Nq 16
#define COUTq 128
#define LOUTq 2048
#define CHUNK 64
#define NCHUNK 128
#define ROWS (Bq*Hq)
#define NCH 512

// ---------------- scratch (static device arrays; no allocation) ----------------
__device__ float  g_y[(size_t)ROWS*Lq];              // 64 MB: SSM output y (B,H,L)
__device__ float2 g_f[(size_t)ROWS*NCHUNK*Nq];       // chunk-final local states
__device__ float2 g_carry[(size_t)ROWS*NCHUNK*Nq];   // chunk initial carries
__device__ float2 g_lam[Hq*Nq];                      // lambda = exp(dt*A)
__device__ float2 g_lamP[Hq*Nq];                     // lambda^CHUNK
__device__ float2 g_cb2[Hq*Nq];                      // 2*C*dB
__device__ float  g_wt[4*Hq*3*COUTq];                // weights transposed [br][h][k][co]
__device__ float  g_scale[NCH];
__device__ float  g_shift[NCH];

// ---------------- derived SSM parameters (tiny; double precision) ----------------
__global__ void k_params(const float* __restrict__ log_dt, const float* __restrict__ A_log,
                         const float* __restrict__ A_imag, const float* __restrict__ B_re,
                         const float* __restrict__ B_im, const float* __restrict__ C_re,
                         const float* __restrict__ C_im) {
    int i = blockIdx.x * blockDim.x + threadIdx.x;
    if (i >= Hq * Nq) return;
    int h = i >> 4;
    double dt = exp((double)log_dt[h]);
    double Ar = -exp((double)A_log[i]);
    double Ai = (double)A_imag[i];
    double dr = dt * Ar, di = dt * Ai;
    double er = exp(dr);
    double lr = er * cos(di), li = er * sin(di);
    g_lam[i] = make_float2((float)lr, (float)li);
    double erP = exp(dr * CHUNK);
    g_lamP[i] = make_float2((float)(erP * cos(di * CHUNK)), (float)(erP * sin(di * CHUNK)));
    // dB = (lambda - 1)/A * (B_re + i*B_im)
    double nr = lr - 1.0, ni = li;
    double den = Ar * Ar + Ai * Ai;
    double qr = (nr * Ar + ni * Ai) / den;
    double qi = (ni * Ar - nr * Ai) / den;
    double br = (double)B_re[i], bi = (double)B_im[i];
    double dBr = qr * br - qi * bi, dBi = qr * bi + qi * br;
    double cr = (double)C_re[i], ci = (double)C_im[i];
    g_cb2[i] = make_float2((float)(2.0 * (cr * dBr - ci * dBi)),
                           (float)(2.0 * (cr * dBi + ci * dBr)));
}

// ---------------- weight transpose: w[co][h][k] -> g_wt[br][h][k][co] ----------------
__global__ void k_wtrans(const float* __restrict__ w1, const float* __restrict__ w2,
                         const float* __restrict__ w3, const float* __restrict__ w4) {
    int o = blockIdx.x * blockDim.x + threadIdx.x;
    if (o >= 4 * Hq * 3 * COUTq) return;
    int co = o & 127;
    int r = o >> 7;
    int k = r % 3; r /= 3;
    int h = r & 127;
    int br = r >> 7;
    const float* w = (br == 0) ? w1 : (br == 1) ? w2 : (br == 2) ? w3 : w4;
    g_wt[o] = w[(co * Hq + h) * 3 + k];
}

// ---------------- phase 1: per-chunk final states ----------------
__global__ __launch_bounds__(NCHUNK) void k_scan1(const float* __restrict__ x) {
    __shared__ float xs[Lq];
    int row = blockIdx.x;
    int h = row & (Hq - 1);
    int c = threadIdx.x;
    const float4* xr = (const float4*)(x + (size_t)row * Lq);
    float4* xs4 = (float4*)xs;
    #pragma unroll
    for (int i = c; i < Lq / 4; i += NCHUNK) xs4[i] = xr[i];
    float lr[Nq], li[Nq];
    #pragma unroll
    for (int n = 0; n < Nq; n++) { float2 v = g_lam[h * Nq + n]; lr[n] = v.x; li[n] = v.y; }
    __syncthreads();
    float sr[Nq], si[Nq];
    #pragma unroll
    for (int n = 0; n < Nq; n++) { sr[n] = 0.f; si[n] = 0.f; }
    int base = c * CHUNK;
    for (int j = 0; j < CHUNK; j++) {
        float xv = xs[base + j];
        #pragma unroll
        for (int n = 0; n < Nq; n++) {
            float nr = fmaf(lr[n], sr[n], xv);
            nr = fmaf(-li[n], si[n], nr);
            float ni = fmaf(lr[n], si[n], li[n] * sr[n]);
            sr[n] = nr; si[n] = ni;
        }
    }
    float2* fo = g_f + ((size_t)row * NCHUNK + c) * Nq;
    #pragma unroll
    for (int n = 0; n < Nq; n++) fo[n] = make_float2(sr[n], si[n]);
}

// ---------------- phase 2: carry prefix across chunks ----------------
__global__ void k_scan2() {
    int t = blockIdx.x * blockDim.x + threadIdx.x;
    if (t >= ROWS * Nq) return;
    int row = t >> 4;
    int n = t & 15;
    int h = row & (Hq - 1);
    float2 Lp = g_lamP[h * Nq + n];
    float cr = 0.f, ci = 0.f;
    const float2* f = g_f + (size_t)row * NCHUNK * Nq + n;
    float2* cy = g_carry + (size_t)row * NCHUNK * Nq + n;
    for (int c = 0; c < NCHUNK; c++) {
        cy[(size_t)c * Nq] = make_float2(cr, ci);
        float2 fv = f[(size_t)c * Nq];
        float nr = fmaf(Lp.x, cr, fv.x); nr = fmaf(-Lp.y, ci, nr);
        float ni = fmaf(Lp.x, ci, fv.y); ni = fmaf(Lp.y, cr, ni);
        cr = nr; ci = ni;
    }
}

// ---------------- phase 3: full scan with carries, emit y ----------------
__global__ __launch_bounds__(NCHUNK) void k_scan3(const float* __restrict__ x,
                                                  const float* __restrict__ Dv) {
    __shared__ float xs[Lq];
    int row = blockIdx.x;
    int h = row & (Hq - 1);
    int c = threadIdx.x;
    const float4* xr = (const float4*)(x + (size_t)row * Lq);
    float4* xs4 = (float4*)xs;
    #pragma unroll
    for (int i = c; i < Lq / 4; i += NCHUNK) xs4[i] = xr[i];
    float lr[Nq], li[Nq], cbr[Nq], cbi[Nq];
    #pragma unroll
    for (int n = 0; n < Nq; n++) {
        float2 v = g_lam[h * Nq + n]; lr[n] = v.x; li[n] = v.y;
        float2 w = g_cb2[h * Nq + n]; cbr[n] = w.x; cbi[n] = w.y;
    }
    float sr[Nq], si[Nq];
    const float2* cy = g_carry + ((size_t)row * NCHUNK + c) * Nq;
    #pragma unroll
    for (int n = 0; n < Nq; n++) { float2 v = cy[n]; sr[n] = v.x; si[n] = v.y; }
    float Dh = Dv[h];
    __syncthreads();
    int base = c * CHUNK;
    for (int j = 0; j < CHUNK; j++) {
        float xv = xs[base + j];
        float acc = Dh * xv;
        #pragma unroll
        for (int n = 0; n < Nq; n++) {
            float nr = fmaf(lr[n], sr[n], xv);
            nr = fmaf(-li[n], si[n], nr);
            float ni = fmaf(lr[n], si[n], li[n] * sr[n]);
            sr[n] = nr; si[n] = ni;
            acc = fmaf(cbr[n], nr, acc);
            acc = fmaf(-cbi[n], ni, acc);
        }
        xs[base + j] = acc;   // each thread owns its 64-elem segment
    }
    __syncthreads();
    float4* yr = (float4*)(g_y + (size_t)row * Lq);
    #pragma unroll
    for (int i = c; i < Lq / 4; i += NCHUNK) yr[i] = xs4[i];
}

// ---------------- dilated strided conv (per branch), bias + leaky-relu, writes pre-BN z ----------------
__global__ __launch_bounds__(128) void k_conv(const float* __restrict__ b1,
                                              const float* __restrict__ b2,
                                              const float* __restrict__ b3,
                                              const float* __restrict__ b4,
                                              float* __restrict__ out) {
    __shared__ float smem[8320];           // 8*273 during compute, 128*65 during store
    int tt = blockIdx.x;                   // 32 t-tiles of 64
    int br = blockIdx.y;                   // 4 branches
    int b  = blockIdx.z;                   // 16 batch
    int d = 1 << br;                       // dilation = padding
    int t0 = tt * 64;
    int pstart = 4 * t0 - d;
    int W = 256 + 2 * d;
    int tid = threadIdx.x;
    int cg = tid & 31;                     // co group
    int tq = tid >> 5;                     // t quarter
    float acc[4][16];
    #pragma unroll
    for (int ci = 0; ci < 4; ci++)
        #pragma unroll
        for (int tl = 0; tl < 16; tl++) acc[ci][tl] = 0.f;

    const float* wt = g_wt + br * Hq * 3 * COUTq;
    const float* yb = g_y + (size_t)b * Hq * Lq;

    for (int hb = 0; hb < Hq / 8; hb++) {
        __syncthreads();
        for (int idx = tid; idx < 8 * W; idx += 128) {
            int hh = idx / W;
            int p = idx - hh * W;
            int gp = pstart + p;
            float v = 0.f;
            if (gp >= 0 && gp < Lq) v = yb[(size_t)(hb * 8 + hh) * Lq + gp];
            smem[hh * 273 + p] = v;
        }
        __syncthreads();
        #pragma unroll
        for (int hh = 0; hh < 8; hh++) {
            int h = hb * 8 + hh;
            float wv[3][4];
            #pragma unroll
            for (int k = 0; k < 3; k++)
                #pragma unroll
                for (int ci = 0; ci < 4; ci++)
                    wv[k][ci] = wt[(h * 3 + k) * COUTq + cg + ci * 32];
            const float* ysr = smem + hh * 273 + tq * 64;
            #pragma unroll
            for (int tl = 0; tl < 16; tl++) {
                #pragma unroll
                for (int k = 0; k < 3; k++) {
                    float yv = ysr[4 * tl + k * d];   // broadcast across co-lanes
                    #pragma unroll
                    for (int ci = 0; ci < 4; ci++)
                        acc[ci][tl] = fmaf(wv[k][ci], yv, acc[ci][tl]);
                }
            }
        }
    }
    const float* bias = (br == 0) ? b1 : (br == 1) ? b2 : (br == 2) ? b3 : b4;
    __syncthreads();
    #pragma unroll
    for (int ci = 0; ci < 4; ci++) {
        int co = cg + ci * 32;
        float bv = bias[co];
        #pragma unroll
        for (int tl = 0; tl < 16; tl++) {
            float v = acc[ci][tl] + bv;
            if (br > 0 && v < 0.f) v *= 0.3f;   // leaky relu before BN (branches 2-4)
            smem[co * 65 + tq * 16 + tl] = v;
        }
    }
    __syncthreads();
    float* ob = out + ((size_t)b * NCH + br * COUTq) * LOUTq + t0;
    for (int i = tid; i < 8192; i += 128) {
        int co = i >> 6, t = i & 63;
        ob[(size_t)co * LOUTq + t] = smem[co * 65 + t];
    }
}

// ---------------- BN: per-channel mean/var -> fused scale/shift ----------------
__global__ void k_bnstats(const float* __restrict__ out, const float* __restrict__ gamma,
                          const float* __restrict__ beta) {
    __shared__ float ssum[256], ssq[256];
    int ch = blockIdx.x;
    int tid = threadIdx.x;
    float s = 0.f, s2 = 0.f;
    const float* base = out + (size_t)ch * LOUTq;
    for (int i = tid; i < Bq * LOUTq; i += 256) {
        int b = i >> 11, t = i & 2047;
        float v = base[(size_t)b * NCH * LOUTq + t];
        s += v;
        s2 = fmaf(v, v, s2);
    }
    ssum[tid] = s; ssq[tid] = s2;
    __syncthreads();
    for (int st = 128; st > 0; st >>= 1) {
        if (tid < st) { ssum[tid] += ssum[tid + st]; ssq[tid] += ssq[tid + st]; }
        __syncthreads();
    }
    if (tid == 0) {
        const float inv = 1.f / (float)(Bq * LOUTq);
        float m = ssum[0] * inv;
        float var = ssq[0] * inv - m * m;
        float rstd = rsqrtf(var + 1e-5f);
        float sc = gamma[ch & 127] * rstd;
        g_scale[ch] = sc;
        g_shift[ch] = beta[ch & 127] - m * sc;
    }
}

__global__ void k_bnapply(float* __restrict__ out) {
    const int total4 = Bq * NCH * LOUTq / 4;
    float4* o4 = (float4*)out;
    for (int i = blockIdx.x * blockDim.x + threadIdx.x; i < total4; i += gridDim.x * blockDim.x) {
        int ch = (i >> 9) & (NCH - 1);      // 512 float4 per (b,ch) row
        float sc = g_scale[ch], sh = g_shift[ch];
        float4 v = o4[i];
        v.x = fmaf(v.x, sc, sh);
        v.y = fmaf(v.y, sc, sh);
        v.z = fmaf(v.z, sc, sh);
        v.w = fmaf(v.w, sc, sh);
        o4[i] = v;
    }
}

// ---------------- launch ----------------
extern "C" void kernel_launch(void* const* d_in, const int* in_sizes, int n_in,
                              void* d_out, int out_size) {
    (void)in_sizes; (void)n_in; (void)out_size;
    const float* x      = (const float*)d_in[0];
    const float* log_dt = (const float*)d_in[1];
    const float* A_log  = (const float*)d_in[2];
    const float* A_imag = (const float*)d_in[3];
    const float* B_re   = (const float*)d_in[4];
    const float* B_im   = (const float*)d_in[5];
    const float* C_re   = (const float*)d_in[6];
    const float* C_im   = (const float*)d_in[7];
    const float* Dv     = (const float*)d_in[8];
    const float* w1 = (const float*)d_in[9];
    const float* b1 = (const float*)d_in[10];
    const float* w2 = (const float*)d_in[11];
    const float* b2 = (const float*)d_in[12];
    const float* w3 = (const float*)d_in[13];
    const float* b3 = (const float*)d_in[14];
    const float* w4 = (const float*)d_in[15];
    const float* b4 = (const float*)d_in[16];
    const float* gamma = (const float*)d_in[17];
    const float* beta  = (const float*)d_in[18];
    float* out = (float*)d_out;

    k_params<<<(Hq * Nq + 255) / 256, 256>>>(log_dt, A_log, A_imag, B_re, B_im, C_re, C_im);
    k_wtrans<<<(4 * Hq * 3 * COUTq + 255) / 256, 256>>>(w1, w2, w3, w4);
    k_scan1<<<ROWS, NCHUNK>>>(x);
    k_scan2<<<(ROWS * Nq + 255) / 256, 256>>>();
    k_scan3<<<ROWS, NCHUNK>>>(x, Dv);
    k_conv<<<dim3(LOUTq / 64, 4, Bq), 128>>>(b1, b2, b3, b4, out);
    k_bnstats<<<NCH, 256>>>(out, gamma, beta);
    k_bnapply<<<4096, 256>>>(out);
}

// round 13
// speedup vs baseline: 1.0035x; 1.0035x over previous
#include <cuda_runtime.h>
#include <math.h>

#define Bq 16
#define Hq 128
#define Lq 8192
#define Nq 16
#define COUTq 128
#define LOUTq 2048
#define CHUNK 64
#define NCHUNK 128
#define ROWS (Bq*Hq)
#define NCH 512

// ---------------- scratch (static device arrays; no allocation) ----------------
__device__ float  g_y[(size_t)ROWS*Lq];              // 64 MB: SSM output y (B,H,L)
__device__ float2 g_f[(size_t)ROWS*NCHUNK*Nq];       // chunk-final local states
__device__ float2 g_carry[(size_t)ROWS*NCHUNK*Nq];   // chunk initial carries
__device__ float2 g_lam[Hq*Nq];                      // lambda = exp(dt*A)
__device__ float2 g_lamP[Hq*Nq];                     // lambda^CHUNK
__device__ float2 g_cb2[Hq*Nq];                      // 2*C*dB
__device__ float  g_wt[4*Hq*3*COUTq];                // weights transposed [br][h][k][co]
__device__ float  g_scale[NCH];
__device__ float  g_shift[NCH];

// ---------------- derived SSM parameters (tiny; double precision) ----------------
__global__ void k_params(const float* __restrict__ log_dt, const float* __restrict__ A_log,
                         const float* __restrict__ A_imag, const float* __restrict__ B_re,
                         const float* __restrict__ B_im, const float* __restrict__ C_re,
                         const float* __restrict__ C_im) {
    int i = blockIdx.x * blockDim.x + threadIdx.x;
    if (i >= Hq * Nq) return;
    int h = i >> 4;
    double dt = exp((double)log_dt[h]);
    double Ar = -exp((double)A_log[i]);
    double Ai = (double)A_imag[i];
    double dr = dt * Ar, di = dt * Ai;
    double er = exp(dr);
    double lr = er * cos(di), li = er * sin(di);
    g_lam[i] = make_float2((float)lr, (float)li);
    double erP = exp(dr * CHUNK);
    g_lamP[i] = make_float2((float)(erP * cos(di * CHUNK)), (float)(erP * sin(di * CHUNK)));
    // dB = (lambda - 1)/A * (B_re + i*B_im)
    double nr = lr - 1.0, ni = li;
    double den = Ar * Ar + Ai * Ai;
    double qr = (nr * Ar + ni * Ai) / den;
    double qi = (ni * Ar - nr * Ai) / den;
    double br = (double)B_re[i], bi = (double)B_im[i];
    double dBr = qr * br - qi * bi, dBi = qr * bi + qi * br;
    double cr = (double)C_re[i], ci = (double)C_im[i];
    g_cb2[i] = make_float2((float)(2.0 * (cr * dBr - ci * dBi)),
                           (float)(2.0 * (cr * dBi + ci * dBr)));
}

// ---------------- weight transpose: w[co][h][k] -> g_wt[br][h][k][co] ----------------
__global__ void k_wtrans(const float* __restrict__ w1, const float* __restrict__ w2,
                         const float* __restrict__ w3, const float* __restrict__ w4) {
    int o = blockIdx.x * blockDim.x + threadIdx.x;
    if (o >= 4 * Hq * 3 * COUTq) return;
    int co = o & 127;
    int r = o >> 7;
    int k = r % 3; r /= 3;
    int h = r & 127;
    int br = r >> 7;
    const float* w = (br == 0) ? w1 : (br == 1) ? w2 : (br == 2) ? w3 : w4;
    g_wt[o] = w[(co * Hq + h) * 3 + k];
}

// ---------------- phase 1: per-chunk final states ----------------
__global__ __launch_bounds__(NCHUNK) void k_scan1(const float* __restrict__ x) {
    __shared__ float xs[Lq];
    int row = blockIdx.x;
    int h = row & (Hq - 1);
    int c = threadIdx.x;
    const float4* xr = (const float4*)(x + (size_t)row * Lq);
    float4* xs4 = (float4*)xs;
    #pragma unroll
    for (int i = c; i < Lq / 4; i += NCHUNK) xs4[i] = xr[i];
    float lr[Nq], li[Nq];
    #pragma unroll
    for (int n = 0; n < Nq; n++) { float2 v = g_lam[h * Nq + n]; lr[n] = v.x; li[n] = v.y; }
    __syncthreads();
    float sr[Nq], si[Nq];
    #pragma unroll
    for (int n = 0; n < Nq; n++) { sr[n] = 0.f; si[n] = 0.f; }
    int base = c * CHUNK;
    for (int j = 0; j < CHUNK; j++) {
        float xv = xs[base + j];
        #pragma unroll
        for (int n = 0; n < Nq; n++) {
            float nr = fmaf(lr[n], sr[n], xv);
            nr = fmaf(-li[n], si[n], nr);
            float ni = fmaf(lr[n], si[n], li[n] * sr[n]);
            sr[n] = nr; si[n] = ni;
        }
    }
    float2* fo = g_f + ((size_t)row * NCHUNK + c) * Nq;
    #pragma unroll
    for (int n = 0; n < Nq; n++) fo[n] = make_float2(sr[n], si[n]);
}

// ---------------- phase 2: carry prefix across chunks ----------------
__global__ void k_scan2() {
    int t = blockIdx.x * blockDim.x + threadIdx.x;
    if (t >= ROWS * Nq) return;
    int row = t >> 4;
    int n = t & 15;
    int h = row & (Hq - 1);
    float2 Lp = g_lamP[h * Nq + n];
    float cr = 0.f, ci = 0.f;
    const float2* f = g_f + (size_t)row * NCHUNK * Nq + n;
    float2* cy = g_carry + (size_t)row * NCHUNK * Nq + n;
    for (int c = 0; c < NCHUNK; c++) {
        cy[(size_t)c * Nq] = make_float2(cr, ci);
        float2 fv = f[(size_t)c * Nq];
        float nr = fmaf(Lp.x, cr, fv.x); nr = fmaf(-Lp.y, ci, nr);
        float ni = fmaf(Lp.x, ci, fv.y); ni = fmaf(Lp.y, cr, ni);
        cr = nr; ci = ni;
    }
}

// ---------------- phase 3: full scan with carries, emit y ----------------
__global__ __launch_bounds__(NCHUNK) void k_scan3(const float* __restrict__ x,
                                                  const float* __restrict__ Dv) {
    __shared__ float xs[Lq];
    int row = blockIdx.x;
    int h = row & (Hq - 1);
    int c = threadIdx.x;
    const float4* xr = (const float4*)(x + (size_t)row * Lq);
    float4* xs4 = (float4*)xs;
    #pragma unroll
    for (int i = c; i < Lq / 4; i += NCHUNK) xs4[i] = xr[i];
    float lr[Nq], li[Nq], cbr[Nq], cbi[Nq];
    #pragma unroll
    for (int n = 0; n < Nq; n++) {
        float2 v = g_lam[h * Nq + n]; lr[n] = v.x; li[n] = v.y;
        float2 w = g_cb2[h * Nq + n]; cbr[n] = w.x; cbi[n] = w.y;
    }
    float sr[Nq], si[Nq];
    const float2* cy = g_carry + ((size_t)row * NCHUNK + c) * Nq;
    #pragma unroll
    for (int n = 0; n < Nq; n++) { float2 v = cy[n]; sr[n] = v.x; si[n] = v.y; }
    float Dh = Dv[h];
    __syncthreads();
    int base = c * CHUNK;
    for (int j = 0; j < CHUNK; j++) {
        float xv = xs[base + j];
        float acc = Dh * xv;
        #pragma unroll
        for (int n = 0; n < Nq; n++) {
            float nr = fmaf(lr[n], sr[n], xv);
            nr = fmaf(-li[n], si[n], nr);
            float ni = fmaf(lr[n], si[n], li[n] * sr[n]);
            sr[n] = nr; si[n] = ni;
            acc = fmaf(cbr[n], nr, acc);
            acc = fmaf(-cbi[n], ni, acc);
        }
        xs[base + j] = acc;   // each thread owns its 64-elem segment
    }
    __syncthreads();
    float4* yr = (float4*)(g_y + (size_t)row * Lq);
    #pragma unroll
    for (int i = c; i < Lq / 4; i += NCHUNK) yr[i] = xs4[i];
}

// ---------------- dilated strided conv (per branch), bias + leaky-relu, writes pre-BN z ----------------
__global__ __launch_bounds__(128) void k_conv(const float* __restrict__ b1,
                                              const float* __restrict__ b2,
                                              const float* __restrict__ b3,
                                              const float* __restrict__ b4,
                                              float* __restrict__ out) {
    __shared__ float smem[8320];           // 8*273 during compute, 128*65 during store
    int tt = blockIdx.x;                   // 32 t-tiles of 64
    int br = blockIdx.y;                   // 4 branches
    int b  = blockIdx.z;                   // 16 batch
    int d = 1 << br;                       // dilation = padding
    int t0 = tt * 64;
    int pstart = 4 * t0 - d;
    int W = 256 + 2 * d;
    int tid = threadIdx.x;
    int cg = tid & 31;                     // co group
    int tq = tid >> 5;                     // t quarter
    float acc[4][16];
    #pragma unroll
    for (int ci = 0; ci < 4; ci++)
        #pragma unroll
        for (int tl = 0; tl < 16; tl++) acc[ci][tl] = 0.f;

    const float* wt = g_wt + br * Hq * 3 * COUTq;
    const float* yb = g_y + (size_t)b * Hq * Lq;

    for (int hb = 0; hb < Hq / 8; hb++) {
        __syncthreads();
        for (int idx = tid; idx < 8 * W; idx += 128) {
            int hh = idx / W;
            int p = idx - hh * W;
            int gp = pstart + p;
            float v = 0.f;
            if (gp >= 0 && gp < Lq) v = yb[(size_t)(hb * 8 + hh) * Lq + gp];
            smem[hh * 273 + p] = v;
        }
        __syncthreads();
        #pragma unroll
        for (int hh = 0; hh < 8; hh++) {
            int h = hb * 8 + hh;
            float wv[3][4];
            #pragma unroll
            for (int k = 0; k < 3; k++)
                #pragma unroll
                for (int ci = 0; ci < 4; ci++)
                    wv[k][ci] = wt[(h * 3 + k) * COUTq + cg + ci * 32];
            const float* ysr = smem + hh * 273 + tq * 64;
            #pragma unroll
            for (int tl = 0; tl < 16; tl++) {
                #pragma unroll
                for (int k = 0; k < 3; k++) {
                    float yv = ysr[4 * tl + k * d];   // broadcast across co-lanes
                    #pragma unroll
                    for (int ci = 0; ci < 4; ci++)
                        acc[ci][tl] = fmaf(wv[k][ci], yv, acc[ci][tl]);
                }
            }
        }
    }
    const float* bias = (br == 0) ? b1 : (br == 1) ? b2 : (br == 2) ? b3 : b4;
    __syncthreads();
    #pragma unroll
    for (int ci = 0; ci < 4; ci++) {
        int co = cg + ci * 32;
        float bv = bias[co];
        #pragma unroll
        for (int tl = 0; tl < 16; tl++) {
            float v = acc[ci][tl] + bv;
            if (br > 0 && v < 0.f) v *= 0.3f;   // leaky relu before BN (branches 2-4)
            smem[co * 65 + tq * 16 + tl] = v;
        }
    }
    __syncthreads();
    float* ob = out + ((size_t)b * NCH + br * COUTq) * LOUTq + t0;
    for (int i = tid; i < 8192; i += 128) {
        int co = i >> 6, t = i & 63;
        ob[(size_t)co * LOUTq + t] = smem[co * 65 + t];
    }
}

// ---------------- BN: per-channel mean/var -> fused scale/shift ----------------
__global__ void k_bnstats(const float* __restrict__ out, const float* __restrict__ gamma,
                          const float* __restrict__ beta) {
    __shared__ float ssum[256], ssq[256];
    int ch = blockIdx.x;
    int tid = threadIdx.x;
    float s = 0.f, s2 = 0.f;
    const float* base = out + (size_t)ch * LOUTq;
    for (int i = tid; i < Bq * LOUTq; i += 256) {
        int b = i >> 11, t = i & 2047;
        float v = base[(size_t)b * NCH * LOUTq + t];
        s += v;
        s2 = fmaf(v, v, s2);
    }
    ssum[tid] = s; ssq[tid] = s2;
    __syncthreads();
    for (int st = 128; st > 0; st >>= 1) {
        if (tid < st) { ssum[tid] += ssum[tid + st]; ssq[tid] += ssq[tid + st]; }
        __syncthreads();
    }
    if (tid == 0) {
        const float inv = 1.f / (float)(Bq * LOUTq);
        float m = ssum[0] * inv;
        float var = ssq[0] * inv - m * m;
        float rstd = rsqrtf(var + 1e-5f);
        float sc = gamma[ch & 127] * rstd;
        g_scale[ch] = sc;
        g_shift[ch] = beta[ch & 127] - m * sc;
    }
}

__global__ void k_bnapply(float* __restrict__ out) {
    const int total4 = Bq * NCH * LOUTq / 4;
    float4* o4 = (float4*)out;
    for (int i = blockIdx.x * blockDim.x + threadIdx.x; i < total4; i += gridDim.x * blockDim.x) {
        int ch = (i >> 9) & (NCH - 1);      // 512 float4 per (b,ch) row
        float sc = g_scale[ch], sh = g_shift[ch];
        float4 v = o4[i];
        v.x = fmaf(v.x, sc, sh);
        v.y = fmaf(v.y, sc, sh);
        v.z = fmaf(v.z, sc, sh);
        v.w = fmaf(v.w, sc, sh);
        o4[i] = v;
    }
}

// ---------------- launch ----------------
extern "C" void kernel_launch(void* const* d_in, const int* in_sizes, int n_in,
                              void* d_out, int out_size) {
    (void)in_sizes; (void)n_in; (void)out_size;
    const float* x      = (const float*)d_in[0];
    const float* log_dt = (const float*)d_in[1];
    const float* A_log  = (const float*)d_in[2];
    const float* A_imag = (const float*)d_in[3];
    const float* B_re   = (const float*)d_in[4];
    const float* B_im   = (const float*)d_in[5];
    const float* C_re   = (const float*)d_in[6];
    const float* C_im   = (const float*)d_in[7];
    const float* Dv     = (const float*)d_in[8];
    const float* w1 = (const float*)d_in[9];
    const float* b1 = (const float*)d_in[10];
    const float* w2 = (const float*)d_in[11];
    const float* b2 = (const float*)d_in[12];
    const float* w3 = (const float*)d_in[13];
    const float* b3 = (const float*)d_in[14];
    const float* w4 = (const float*)d_in[15];
    const float* b4 = (const float*)d_in[16];
    const float* gamma = (const float*)d_in[17];
    const float* beta  = (const float*)d_in[18];
    float* out = (float*)d_out;

    k_params<<<(Hq * Nq + 255) / 256, 256>>>(log_dt, A_log, A_imag, B_re, B_im, C_re, C_im);
    k_wtrans<<<(4 * Hq * 3 * COUTq + 255) / 256, 256>>>(w1, w2, w3, w4);
    k_scan1<<<ROWS, NCHUNK>>>(x);
    k_scan2<<<(ROWS * Nq + 255) / 256, 256>>>();
    k_scan3<<<ROWS, NCHUNK>>>(x, Dv);
    k_conv<<<dim3(LOUTq / 64, 4, Bq), 128>>>(b1, b2, b3, b4, out);
    k_bnstats<<<NCH, 256>>>(out, gamma, beta);
    k_bnapply<<<4096, 256>>>(out);
}

// round 14
// speedup vs baseline: 1.0072x; 1.0037x over previous
#include <cuda_runtime.h>
#include <math.h>

#define Bq 16
#define Hq 128
#define Lq 8192
#define Nq 16
#define COUTq 128
#define LOUTq 2048
#define CHUNK 64
#define NCHUNK 128
#define ROWS (Bq*Hq)
#define NCH 512

// ---------------- scratch (static device arrays; no allocation) ----------------
__device__ float  g_y[(size_t)ROWS*Lq];              // 64 MB: SSM output y (B,H,L)
__device__ float2 g_f[(size_t)ROWS*NCHUNK*Nq];       // chunk-final local states
__device__ float2 g_carry[(size_t)ROWS*NCHUNK*Nq];   // chunk initial carries
__device__ float2 g_lam[Hq*Nq];                      // lambda = exp(dt*A)
__device__ float2 g_lamP[Hq*Nq];                     // lambda^CHUNK
__device__ float2 g_cb2[Hq*Nq];                      // 2*C*dB
__device__ float  g_wt[4*Hq*3*COUTq];                // weights transposed [br][h][k][co]
__device__ float  g_scale[NCH];
__device__ float  g_shift[NCH];

// ---------------- derived SSM parameters (tiny; double precision) ----------------
__global__ void k_params(const float* __restrict__ log_dt, const float* __restrict__ A_log,
                         const float* __restrict__ A_imag, const float* __restrict__ B_re,
                         const float* __restrict__ B_im, const float* __restrict__ C_re,
                         const float* __restrict__ C_im) {
    int i = blockIdx.x * blockDim.x + threadIdx.x;
    if (i >= Hq * Nq) return;
    int h = i >> 4;
    double dt = exp((double)log_dt[h]);
    double Ar = -exp((double)A_log[i]);
    double Ai = (double)A_imag[i];
    double dr = dt * Ar, di = dt * Ai;
    double er = exp(dr);
    double lr = er * cos(di), li = er * sin(di);
    g_lam[i] = make_float2((float)lr, (float)li);
    double erP = exp(dr * CHUNK);
    g_lamP[i] = make_float2((float)(erP * cos(di * CHUNK)), (float)(erP * sin(di * CHUNK)));
    // dB = (lambda - 1)/A * (B_re + i*B_im)
    double nr = lr - 1.0, ni = li;
    double den = Ar * Ar + Ai * Ai;
    double qr = (nr * Ar + ni * Ai) / den;
    double qi = (ni * Ar - nr * Ai) / den;
    double br = (double)B_re[i], bi = (double)B_im[i];
    double dBr = qr * br - qi * bi, dBi = qr * bi + qi * br;
    double cr = (double)C_re[i], ci = (double)C_im[i];
    g_cb2[i] = make_float2((float)(2.0 * (cr * dBr - ci * dBi)),
                           (float)(2.0 * (cr * dBi + ci * dBr)));
}

// ---------------- weight transpose: w[co][h][k] -> g_wt[br][h][k][co] ----------------
__global__ void k_wtrans(const float* __restrict__ w1, const float* __restrict__ w2,
                         const float* __restrict__ w3, const float* __restrict__ w4) {
    int o = blockIdx.x * blockDim.x + threadIdx.x;
    if (o >= 4 * Hq * 3 * COUTq) return;
    int co = o & 127;
    int r = o >> 7;
    int k = r % 3; r /= 3;
    int h = r & 127;
    int br = r >> 7;
    const float* w = (br == 0) ? w1 : (br == 1) ? w2 : (br == 2) ? w3 : w4;
    g_wt[o] = w[(co * Hq + h) * 3 + k];
}

// ---------------- phase 1: per-chunk final states ----------------
__global__ __launch_bounds__(NCHUNK) void k_scan1(const float* __restrict__ x) {
    __shared__ float xs[Lq];
    int row = blockIdx.x;
    int h = row & (Hq - 1);
    int c = threadIdx.x;
    const float4* xr = (const float4*)(x + (size_t)row * Lq);
    float4* xs4 = (float4*)xs;
    #pragma unroll
    for (int i = c; i < Lq / 4; i += NCHUNK) xs4[i] = xr[i];
    float lr[Nq], li[Nq];
    #pragma unroll
    for (int n = 0; n < Nq; n++) { float2 v = g_lam[h * Nq + n]; lr[n] = v.x; li[n] = v.y; }
    __syncthreads();
    float sr[Nq], si[Nq];
    #pragma unroll
    for (int n = 0; n < Nq; n++) { sr[n] = 0.f; si[n] = 0.f; }
    int base = c * CHUNK;
    for (int j = 0; j < CHUNK; j++) {
        float xv = xs[base + j];
        #pragma unroll
        for (int n = 0; n < Nq; n++) {
            float nr = fmaf(lr[n], sr[n], xv);
            nr = fmaf(-li[n], si[n], nr);
            float ni = fmaf(lr[n], si[n], li[n] * sr[n]);
            sr[n] = nr; si[n] = ni;
        }
    }
    float2* fo = g_f + ((size_t)row * NCHUNK + c) * Nq;
    #pragma unroll
    for (int n = 0; n < Nq; n++) fo[n] = make_float2(sr[n], si[n]);
}

// ---------------- phase 2: carry prefix across chunks ----------------
__global__ void k_scan2() {
    int t = blockIdx.x * blockDim.x + threadIdx.x;
    if (t >= ROWS * Nq) return;
    int row = t >> 4;
    int n = t & 15;
    int h = row & (Hq - 1);
    float2 Lp = g_lamP[h * Nq + n];
    float cr = 0.f, ci = 0.f;
    const float2* f = g_f + (size_t)row * NCHUNK * Nq + n;
    float2* cy = g_carry + (size_t)row * NCHUNK * Nq + n;
    for (int c = 0; c < NCHUNK; c++) {
        cy[(size_t)c * Nq] = make_float2(cr, ci);
        float2 fv = f[(size_t)c * Nq];
        float nr = fmaf(Lp.x, cr, fv.x); nr = fmaf(-Lp.y, ci, nr);
        float ni = fmaf(Lp.x, ci, fv.y); ni = fmaf(Lp.y, cr, ni);
        cr = nr; ci = ni;
    }
}

// ---------------- phase 3: full scan with carries, emit y ----------------
__global__ __launch_bounds__(NCHUNK) void k_scan3(const float* __restrict__ x,
                                                  const float* __restrict__ Dv) {
    __shared__ float xs[Lq];
    int row = blockIdx.x;
    int h = row & (Hq - 1);
    int c = threadIdx.x;
    const float4* xr = (const float4*)(x + (size_t)row * Lq);
    float4* xs4 = (float4*)xs;
    #pragma unroll
    for (int i = c; i < Lq / 4; i += NCHUNK) xs4[i] = xr[i];
    float lr[Nq], li[Nq], cbr[Nq], cbi[Nq];
    #pragma unroll
    for (int n = 0; n < Nq; n++) {
        float2 v = g_lam[h * Nq + n]; lr[n] = v.x; li[n] = v.y;
        float2 w = g_cb2[h * Nq + n]; cbr[n] = w.x; cbi[n] = w.y;
    }
    float sr[Nq], si[Nq];
    const float2* cy = g_carry + ((size_t)row * NCHUNK + c) * Nq;
    #pragma unroll
    for (int n = 0; n < Nq; n++) { float2 v = cy[n]; sr[n] = v.x; si[n] = v.y; }
    float Dh = Dv[h];
    __syncthreads();
    int base = c * CHUNK;
    for (int j = 0; j < CHUNK; j++) {
        float xv = xs[base + j];
        float acc = Dh * xv;
        #pragma unroll
        for (int n = 0; n < Nq; n++) {
            float nr = fmaf(lr[n], sr[n], xv);
            nr = fmaf(-li[n], si[n], nr);
            float ni = fmaf(lr[n], si[n], li[n] * sr[n]);
            sr[n] = nr; si[n] = ni;
            acc = fmaf(cbr[n], nr, acc);
            acc = fmaf(-cbi[n], ni, acc);
        }
        xs[base + j] = acc;   // each thread owns its 64-elem segment
    }
    __syncthreads();
    float4* yr = (float4*)(g_y + (size_t)row * Lq);
    #pragma unroll
    for (int i = c; i < Lq / 4; i += NCHUNK) yr[i] = xs4[i];
}

// ---------------- dilated strided conv (per branch), bias + leaky-relu, writes pre-BN z ----------------
__global__ __launch_bounds__(128) void k_conv(const float* __restrict__ b1,
                                              const float* __restrict__ b2,
                                              const float* __restrict__ b3,
                                              const float* __restrict__ b4,
                                              float* __restrict__ out) {
    __shared__ float smem[8320];           // 8*273 during compute, 128*65 during store
    int tt = blockIdx.x;                   // 32 t-tiles of 64
    int br = blockIdx.y;                   // 4 branches
    int b  = blockIdx.z;                   // 16 batch
    int d = 1 << br;                       // dilation = padding
    int t0 = tt * 64;
    int pstart = 4 * t0 - d;
    int W = 256 + 2 * d;
    int tid = threadIdx.x;
    int cg = tid & 31;                     // co group
    int tq = tid >> 5;                     // t quarter
    float acc[4][16];
    #pragma unroll
    for (int ci = 0; ci < 4; ci++)
        #pragma unroll
        for (int tl = 0; tl < 16; tl++) acc[ci][tl] = 0.f;

    const float* wt = g_wt + br * Hq * 3 * COUTq;
    const float* yb = g_y + (size_t)b * Hq * Lq;

    for (int hb = 0; hb < Hq / 8; hb++) {
        __syncthreads();
        for (int idx = tid; idx < 8 * W; idx += 128) {
            int hh = idx / W;
            int p = idx - hh * W;
            int gp = pstart + p;
            float v = 0.f;
            if (gp >= 0 && gp < Lq) v = yb[(size_t)(hb * 8 + hh) * Lq + gp];
            smem[hh * 273 + p] = v;
        }
        __syncthreads();
        #pragma unroll
        for (int hh = 0; hh < 8; hh++) {
            int h = hb * 8 + hh;
            float wv[3][4];
            #pragma unroll
            for (int k = 0; k < 3; k++)
                #pragma unroll
                for (int ci = 0; ci < 4; ci++)
                    wv[k][ci] = wt[(h * 3 + k) * COUTq + cg + ci * 32];
            const float* ysr = smem + hh * 273 + tq * 64;
            #pragma unroll
            for (int tl = 0; tl < 16; tl++) {
                #pragma unroll
                for (int k = 0; k < 3; k++) {
                    float yv = ysr[4 * tl + k * d];   // broadcast across co-lanes
                    #pragma unroll
                    for (int ci = 0; ci < 4; ci++)
                        acc[ci][tl] = fmaf(wv[k][ci], yv, acc[ci][tl]);
                }
            }
        }
    }
    const float* bias = (br == 0) ? b1 : (br == 1) ? b2 : (br == 2) ? b3 : b4;
    __syncthreads();
    #pragma unroll
    for (int ci = 0; ci < 4; ci++) {
        int co = cg + ci * 32;
        float bv = bias[co];
        #pragma unroll
        for (int tl = 0; tl < 16; tl++) {
            float v = acc[ci][tl] + bv;
            if (br > 0 && v < 0.f) v *= 0.3f;   // leaky relu before BN (branches 2-4)
            smem[co * 65 + tq * 16 + tl] = v;
        }
    }
    __syncthreads();
    float* ob = out + ((size_t)b * NCH + br * COUTq) * LOUTq + t0;
    for (int i = tid; i < 8192; i += 128) {
        int co = i >> 6, t = i & 63;
        ob[(size_t)co * LOUTq + t] = smem[co * 65 + t];
    }
}

// ---------------- BN: per-channel mean/var -> fused scale/shift ----------------
__global__ void k_bnstats(const float* __restrict__ out, const float* __restrict__ gamma,
                          const float* __restrict__ beta) {
    __shared__ float ssum[256], ssq[256];
    int ch = blockIdx.x;
    int tid = threadIdx.x;
    float s = 0.f, s2 = 0.f;
    const float* base = out + (size_t)ch * LOUTq;
    for (int i = tid; i < Bq * LOUTq; i += 256) {
        int b = i >> 11, t = i & 2047;
        float v = base[(size_t)b * NCH * LOUTq + t];
        s += v;
        s2 = fmaf(v, v, s2);
    }
    ssum[tid] = s; ssq[tid] = s2;
    __syncthreads();
    for (int st = 128; st > 0; st >>= 1) {
        if (tid < st) { ssum[tid] += ssum[tid + st]; ssq[tid] += ssq[tid + st]; }
        __syncthreads();
    }
    if (tid == 0) {
        const float inv = 1.f / (float)(Bq * LOUTq);
        float m = ssum[0] * inv;
        float var = ssq[0] * inv - m * m;
        float rstd = rsqrtf(var + 1e-5f);
        float sc = gamma[ch & 127] * rstd;
        g_scale[ch] = sc;
        g_shift[ch] = beta[ch & 127] - m * sc;
    }
}

__global__ void k_bnapply(float* __restrict__ out) {
    const int total4 = Bq * NCH * LOUTq / 4;
    float4* o4 = (float4*)out;
    for (int i = blockIdx.x * blockDim.x + threadIdx.x; i < total4; i += gridDim.x * blockDim.x) {
        int ch = (i >> 9) & (NCH - 1);      // 512 float4 per (b,ch) row
        float sc = g_scale[ch], sh = g_shift[ch];
        float4 v = o4[i];
        v.x = fmaf(v.x, sc, sh);
        v.y = fmaf(v.y, sc, sh);
        v.z = fmaf(v.z, sc, sh);
        v.w = fmaf(v.w, sc, sh);
        o4[i] = v;
    }
}

// ---------------- launch ----------------
extern "C" void kernel_launch(void* const* d_in, const int* in_sizes, int n_in,
                              void* d_out, int out_size) {
    (void)in_sizes; (void)n_in; (void)out_size;
    const float* x      = (const float*)d_in[0];
    const float* log_dt = (const float*)d_in[1];
    const float* A_log  = (const float*)d_in[2];
    const float* A_imag = (const float*)d_in[3];
    const float* B_re   = (const float*)d_in[4];
    const float* B_im   = (const float*)d_in[5];
    const float* C_re   = (const float*)d_in[6];
    const float* C_im   = (const float*)d_in[7];
    const float* Dv     = (const float*)d_in[8];
    const float* w1 = (const float*)d_in[9];
    const float* b1 = (const float*)d_in[10];
    const float* w2 = (const float*)d_in[11];
    const float* b2 = (const float*)d_in[12];
    const float* w3 = (const float*)d_in[13];
    const float* b3 = (const float*)d_in[14];
    const float* w4 = (const float*)d_in[15];
    const float* b4 = (const float*)d_in[16];
    const float* gamma = (const float*)d_in[17];
    const float* beta  = (const float*)d_in[18];
    float* out = (float*)d_out;

    k_params<<<(Hq * Nq + 255) / 256, 256>>>(log_dt, A_log, A_imag, B_re, B_im, C_re, C_im);
    k_wtrans<<<(4 * Hq * 3 * COUTq + 255) / 256, 256>>>(w1, w2, w3, w4);
    k_scan1<<<ROWS, NCHUNK>>>(x);
    k_scan2<<<(ROWS * Nq + 255) / 256, 256>>>();
    k_scan3<<<ROWS, NCHUNK>>>(x, Dv);
    k_conv<<<dim3(LOUTq / 64, 4, Bq), 128>>>(b1, b2, b3, b4, out);
    k_bnstats<<<NCH, 256>>>(out, gamma, beta);
    k_bnapply<<<4096, 256>>>(out);
}

// round 15
// speedup vs baseline: 1.0623x; 1.0547x over previous
#include <cuda_runtime.h>
#include <math.h>

#define Bq 16
#define Hq 128
#define Lq 8192
#define Nq 16
#define COUTq 128
#define LOUTq 2048
#define CHUNK 64
#define NCHUNK 128
#define ROWS (Bq*Hq)
#define NCH 512

// ---------------- scratch (static device arrays; no allocation) ----------------
__device__ float  g_y[(size_t)ROWS*Lq];              // 64 MB: SSM output y (B,H,L)
__device__ float2 g_lam[Hq*Nq];                      // lambda = exp(dt*A)
__device__ float2 g_lamP[Hq*Nq];                     // lambda^CHUNK
__device__ float2 g_cb2[Hq*Nq];                      // 2*C*dB
__device__ float  g_wt[4*Hq*3*COUTq];                // weights transposed [br][h][k][co]
__device__ float2 g_part[(size_t)NCH*Bq*32];         // per-(ch,b,ttile) partial (sum, sumsq)
__device__ float  g_scale[NCH];
__device__ float  g_shift[NCH];

// ---------------- derived SSM parameters (tiny; double precision) ----------------
__global__ void k_params(const float* __restrict__ log_dt, const float* __restrict__ A_log,
                         const float* __restrict__ A_imag, const float* __restrict__ B_re,
                         const float* __restrict__ B_im, const float* __restrict__ C_re,
                         const float* __restrict__ C_im) {
    int i = blockIdx.x * blockDim.x + threadIdx.x;
    if (i >= Hq * Nq) return;
    int h = i >> 4;
    double dt = exp((double)log_dt[h]);
    double Ar = -exp((double)A_log[i]);
    double Ai = (double)A_imag[i];
    double dr = dt * Ar, di = dt * Ai;
    double er = exp(dr);
    double lr = er * cos(di), li = er * sin(di);
    g_lam[i] = make_float2((float)lr, (float)li);
    double erP = exp(dr * CHUNK);
    g_lamP[i] = make_float2((float)(erP * cos(di * CHUNK)), (float)(erP * sin(di * CHUNK)));
    // dB = (lambda - 1)/A * (B_re + i*B_im)
    double nr = lr - 1.0, ni = li;
    double den = Ar * Ar + Ai * Ai;
    double qr = (nr * Ar + ni * Ai) / den;
    double qi = (ni * Ar - nr * Ai) / den;
    double br = (double)B_re[i], bi = (double)B_im[i];
    double dBr = qr * br - qi * bi, dBi = qr * bi + qi * br;
    double cr = (double)C_re[i], ci = (double)C_im[i];
    g_cb2[i] = make_float2((float)(2.0 * (cr * dBr - ci * dBi)),
                           (float)(2.0 * (cr * dBi + ci * dBr)));
}

// ---------------- weight transpose: w[co][h][k] -> g_wt[br][h][k][co] ----------------
__global__ void k_wtrans(const float* __restrict__ w1, const float* __restrict__ w2,
                         const float* __restrict__ w3, const float* __restrict__ w4) {
    int o = blockIdx.x * blockDim.x + threadIdx.x;
    if (o >= 4 * Hq * 3 * COUTq) return;
    int co = o & 127;
    int r = o >> 7;
    int k = r % 3; r /= 3;
    int h = r & 127;
    int br = r >> 7;
    const float* w = (br == 0) ? w1 : (br == 1) ? w2 : (br == 2) ? w3 : w4;
    g_wt[o] = w[(co * Hq + h) * 3 + k];
}

// ---------------- fused 3-phase scan: one block per row, carries via smem log-scan ----------------
__global__ __launch_bounds__(NCHUNK) void k_scan(const float* __restrict__ x,
                                                 const float* __restrict__ Dv) {
    __shared__ float  xs[Lq];                 // 32 KB x/y tile
    __shared__ float2 sf[Nq][NCHUNK];         // 16 KB chunk states / inclusive scan
    int row = blockIdx.x;
    int h = row & (Hq - 1);
    int c = threadIdx.x;                      // chunk index
    const float4* xr = (const float4*)(x + (size_t)row * Lq);
    float4* xs4 = (float4*)xs;
    #pragma unroll
    for (int i = c; i < Lq / 4; i += NCHUNK) xs4[i] = xr[i];

    float lr[Nq], li[Nq], cbr[Nq], cbi[Nq];
    #pragma unroll
    for (int n = 0; n < Nq; n++) {
        float2 v = g_lam[h * Nq + n]; lr[n] = v.x; li[n] = v.y;
        float2 w = g_cb2[h * Nq + n]; cbr[n] = w.x; cbi[n] = w.y;
    }
    float Dh = Dv[h];
    __syncthreads();

    // phase 1: local chunk scan from zero state
    float sr[Nq], si[Nq];
    #pragma unroll
    for (int n = 0; n < Nq; n++) { sr[n] = 0.f; si[n] = 0.f; }
    int base = c * CHUNK;
    for (int j = 0; j < CHUNK; j++) {
        float xv = xs[base + j];
        #pragma unroll
        for (int n = 0; n < Nq; n++) {
            float nr = fmaf(lr[n], sr[n], xv);
            nr = fmaf(-li[n], si[n], nr);
            float ni = fmaf(lr[n], si[n], li[n] * sr[n]);
            sr[n] = nr; si[n] = ni;
        }
    }
    #pragma unroll
    for (int n = 0; n < Nq; n++) sf[n][c] = make_float2(sr[n], si[n]);
    __syncthreads();

    // phase 2: Hillis-Steele inclusive scan over chunks with constant coeff lamP^o.
    // S_c = lamP*S_{c-1} + f_c  <=>  after steps o=1..64: v_c = sum_j lamP^{c-j} f_j
    {
        float2 aP = g_lamP[h * Nq];           // careful: coefficient differs per n
        (void)aP;
    }
    float ar[Nq], ai[Nq];
    #pragma unroll
    for (int n = 0; n < Nq; n++) { float2 v = g_lamP[h * Nq + n]; ar[n] = v.x; ai[n] = v.y; }
    #pragma unroll
    for (int o = 1; o < NCHUNK; o <<= 1) {
        float2 pv[Nq];
        bool act = (c >= o);
        if (act) {
            #pragma unroll
            for (int n = 0; n < Nq; n++) pv[n] = sf[n][c - o];
        }
        __syncthreads();
        if (act) {
            #pragma unroll
            for (int n = 0; n < Nq; n++) {
                float2 v = sf[n][c];
                v.x = fmaf(ar[n], pv[n].x, v.x); v.x = fmaf(-ai[n], pv[n].y, v.x);
                v.y = fmaf(ar[n], pv[n].y, v.y); v.y = fmaf( ai[n], pv[n].x, v.y);
                sf[n][c] = v;
            }
        }
        __syncthreads();
        #pragma unroll
        for (int n = 0; n < Nq; n++) {        // a <- a^2 (complex)
            float nar = fmaf(ar[n], ar[n], -ai[n] * ai[n]);
            ai[n] = 2.f * ar[n] * ai[n];
            ar[n] = nar;
        }
    }

    // carry for chunk c = inclusive state at c-1 (zero for c==0)
    #pragma unroll
    for (int n = 0; n < Nq; n++) {
        float2 v = (c == 0) ? make_float2(0.f, 0.f) : sf[n][c - 1];
        sr[n] = v.x; si[n] = v.y;
    }

    // phase 3: re-scan with injected carry, emit y into xs
    for (int j = 0; j < CHUNK; j++) {
        float xv = xs[base + j];
        float acc = Dh * xv;
        #pragma unroll
        for (int n = 0; n < Nq; n++) {
            float nr = fmaf(lr[n], sr[n], xv);
            nr = fmaf(-li[n], si[n], nr);
            float ni = fmaf(lr[n], si[n], li[n] * sr[n]);
            sr[n] = nr; si[n] = ni;
            acc = fmaf(cbr[n], nr, acc);
            acc = fmaf(-cbi[n], ni, acc);
        }
        xs[base + j] = acc;                   // each thread owns its 64-elem segment
    }
    __syncthreads();
    float4* yr = (float4*)(g_y + (size_t)row * Lq);
    #pragma unroll
    for (int i = c; i < Lq / 4; i += NCHUNK) yr[i] = xs4[i];
}

// ---------------- dilated strided conv (per branch), bias + leaky-relu, writes pre-BN z + BN partials ----------------
__global__ __launch_bounds__(128) void k_conv(const float* __restrict__ b1,
                                              const float* __restrict__ b2,
                                              const float* __restrict__ b3,
                                              const float* __restrict__ b4,
                                              float* __restrict__ out) {
    __shared__ float smem[8320];           // 8*273 during compute, 128*65 during store
    int tt = blockIdx.x;                   // 32 t-tiles of 64
    int br = blockIdx.y;                   // 4 branches
    int b  = blockIdx.z;                   // 16 batch
    int d = 1 << br;                       // dilation = padding
    int t0 = tt * 64;
    int pstart = 4 * t0 - d;
    int W = 256 + 2 * d;
    int tid = threadIdx.x;
    int cg = tid & 31;                     // co group
    int tq = tid >> 5;                     // t quarter
    float acc[4][16];
    #pragma unroll
    for (int ci = 0; ci < 4; ci++)
        #pragma unroll
        for (int tl = 0; tl < 16; tl++) acc[ci][tl] = 0.f;

    const float* wt = g_wt + br * Hq * 3 * COUTq;
    const float* yb = g_y + (size_t)b * Hq * Lq;

    for (int hb = 0; hb < Hq / 8; hb++) {
        __syncthreads();
        for (int idx = tid; idx < 8 * W; idx += 128) {
            int hh = idx / W;
            int p = idx - hh * W;
            int gp = pstart + p;
            float v = 0.f;
            if (gp >= 0 && gp < Lq) v = yb[(size_t)(hb * 8 + hh) * Lq + gp];
            smem[hh * 273 + p] = v;
        }
        __syncthreads();
        #pragma unroll
        for (int hh = 0; hh < 8; hh++) {
            int h = hb * 8 + hh;
            float wv[3][4];
            #pragma unroll
            for (int k = 0; k < 3; k++)
                #pragma unroll
                for (int ci = 0; ci < 4; ci++)
                    wv[k][ci] = wt[(h * 3 + k) * COUTq + cg + ci * 32];
            const float* ysr = smem + hh * 273 + tq * 64;
            #pragma unroll
            for (int tl = 0; tl < 16; tl++) {
                #pragma unroll
                for (int k = 0; k < 3; k++) {
                    float yv = ysr[4 * tl + k * d];   // broadcast across co-lanes
                    #pragma unroll
                    for (int ci = 0; ci < 4; ci++)
                        acc[ci][tl] = fmaf(wv[k][ci], yv, acc[ci][tl]);
                }
            }
        }
    }
    const float* bias = (br == 0) ? b1 : (br == 1) ? b2 : (br == 2) ? b3 : b4;
    __syncthreads();
    #pragma unroll
    for (int ci = 0; ci < 4; ci++) {
        int co = cg + ci * 32;
        float bv = bias[co];
        #pragma unroll
        for (int tl = 0; tl < 16; tl++) {
            float v = acc[ci][tl] + bv;
            if (br > 0 && v < 0.f) v *= 0.3f;   // leaky relu before BN (branches 2-4)
            smem[co * 65 + tq * 16 + tl] = v;
        }
    }
    __syncthreads();
    float* ob = out + ((size_t)b * NCH + br * COUTq) * LOUTq + t0;
    for (int i = tid; i < 8192; i += 128) {
        int co = i >> 6, t = i & 63;
        ob[(size_t)co * LOUTq + t] = smem[co * 65 + t];
    }
    // BN partials: thread tid owns co=tid; stride-65 rows are conflict-free across the warp.
    {
        int co = tid;
        const float* zr = smem + co * 65;
        float s = 0.f, s2 = 0.f;
        #pragma unroll
        for (int t = 0; t < 64; t++) {
            float v = zr[t];
            s += v;
            s2 = fmaf(v, v, s2);
        }
        int ch = br * COUTq + co;                 // matches out channel index
        g_part[(((size_t)ch * Bq + b) << 5) + tt] = make_float2(s, s2);
    }
}

// ---------------- BN: reduce partials -> fused scale/shift (no 128MB re-read) ----------------
__global__ __launch_bounds__(128) void k_bnstats(const float* __restrict__ gamma,
                                                 const float* __restrict__ beta) {
    __shared__ float2 red[128];
    int ch = blockIdx.x;
    int tid = threadIdx.x;
    const float2* p = g_part + (size_t)ch * (Bq * 32);
    float s = 0.f, s2 = 0.f;
    #pragma unroll
    for (int i = 0; i < 4; i++) {              // 512 partials / 128 threads, fixed order
        float2 v = p[tid + i * 128];
        s += v.x; s2 += v.y;
    }
    red[tid] = make_float2(s, s2);
    __syncthreads();
    for (int st = 64; st > 0; st >>= 1) {
        if (tid < st) {
            red[tid].x += red[tid + st].x;
            red[tid].y += red[tid + st].y;
        }
        __syncthreads();
    }
    if (tid == 0) {
        const float inv = 1.f / (float)(Bq * LOUTq);
        float m = red[0].x * inv;
        float var = red[0].y * inv - m * m;
        float rstd = rsqrtf(var + 1e-5f);
        float sc = gamma[ch & 127] * rstd;
        g_scale[ch] = sc;
        g_shift[ch] = beta[ch & 127] - m * sc;
    }
}

__global__ void k_bnapply(float* __restrict__ out) {
    const int total4 = Bq * NCH * LOUTq / 4;
    float4* o4 = (float4*)out;
    for (int i = blockIdx.x * blockDim.x + threadIdx.x; i < total4; i += gridDim.x * blockDim.x) {
        int ch = (i >> 9) & (NCH - 1);      // 512 float4 per (b,ch) row
        float sc = g_scale[ch], sh = g_shift[ch];
        float4 v = o4[i];
        v.x = fmaf(v.x, sc, sh);
        v.y = fmaf(v.y, sc, sh);
        v.z = fmaf(v.z, sc, sh);
        v.w = fmaf(v.w, sc, sh);
        o4[i] = v;
    }
}

// ---------------- launch ----------------
extern "C" void kernel_launch(void* const* d_in, const int* in_sizes, int n_in,
                              void* d_out, int out_size) {
    (void)in_sizes; (void)n_in; (void)out_size;
    const float* x      = (const float*)d_in[0];
    const float* log_dt = (const float*)d_in[1];
    const float* A_log  = (const float*)d_in[2];
    const float* A_imag = (const float*)d_in[3];
    const float* B_re   = (const float*)d_in[4];
    const float* B_im   = (const float*)d_in[5];
    const float* C_re   = (const float*)d_in[6];
    const float* C_im   = (const float*)d_in[7];
    const float* Dv     = (const float*)d_in[8];
    const float* w1 = (const float*)d_in[9];
    const float* b1 = (const float*)d_in[10];
    const float* w2 = (const float*)d_in[11];
    const float* b2 = (const float*)d_in[12];
    const float* w3 = (const float*)d_in[13];
    const float* b3 = (const float*)d_in[14];
    const float* w4 = (const float*)d_in[15];
    const float* b4 = (const float*)d_in[16];
    const float* gamma = (const float*)d_in[17];
    const float* beta  = (const float*)d_in[18];
    float* out = (float*)d_out;

    k_params<<<(Hq * Nq + 255) / 256, 256>>>(log_dt, A_log, A_imag, B_re, B_im, C_re, C_im);
    k_wtrans<<<(4 * Hq * 3 * COUTq + 255) / 256, 256>>>(w1, w2, w3, w4);
    k_scan<<<ROWS, NCHUNK>>>(x, Dv);
    k_conv<<<dim3(LOUTq / 64, 4, Bq), 128>>>(b1, b2, b3, b4, out);
    k_bnstats<<<NCH, 128>>>(gamma, beta);
    k_bnapply<<<4096, 256>>>(out);
}